// round 1
// baseline (speedup 1.0000x reference)
#include <cuda_runtime.h>
#include <cuda_bf16.h>
#include <math.h>

// Problem constants
#define B_ 8
#define C_ 64
#define H_ 128
#define W_ 128
#define HS 256
#define WS 256

// Scratch (no cudaMalloc allowed): mean [8,128,128], weights [8,128,128,4,9]
__device__ float g_mean[B_ * H_ * W_];
__device__ float g_wk[(size_t)B_ * H_ * W_ * 36];

// ---------------------------------------------------------------------------
// K1: channel mean. One thread per (b,y,x). 64 strided loads, coalesced per c.
// ---------------------------------------------------------------------------
__global__ void mean_kernel(const float* __restrict__ x, float* __restrict__ mean)
{
    int idx = blockIdx.x * blockDim.x + threadIdx.x;
    if (idx >= B_ * H_ * W_) return;
    int b = idx >> 14;          // / 16384
    int p = idx & 16383;
    const float* px = x + ((size_t)b << 20) + p;   // b*64*16384
    float s = 0.f;
#pragma unroll
    for (int c = 0; c < C_; c++) s += px[(size_t)c << 14];
    mean[idx] = s * (1.0f / 64.0f);
}

// ---------------------------------------------------------------------------
// K2: per-low-res-pixel reassembly weights.
// conv5x5 on nearest-up(mean) collapses to the 3x3 low-res mean neighborhood.
// Produces softmaxed weights [idx][sub(4)][k(9)].
// ---------------------------------------------------------------------------
__global__ void weights_kernel(const float* __restrict__ mean,
                               const float* __restrict__ w_off,
                               const float* __restrict__ b_off,
                               float* __restrict__ wk)
{
    __shared__ float sw[50];
    __shared__ float sb[2];
    if (threadIdx.x < 50) sw[threadIdx.x] = w_off[threadIdx.x];
    if (threadIdx.x < 2)  sb[threadIdx.x] = b_off[threadIdx.x];
    __syncthreads();

    int idx = blockIdx.x * blockDim.x + threadIdx.x;
    if (idx >= B_ * H_ * W_) return;
    int b  = idx >> 14;
    int y  = (idx >> 7) & 127;
    int xx = idx & 127;

    const float* mb = mean + ((size_t)b << 14);
    float m[3][3];
#pragma unroll
    for (int dr = -1; dr <= 1; dr++)
#pragma unroll
        for (int dc = -1; dc <= 1; dc++) {
            int yy = y + dr, xc = xx + dc;
            m[dr + 1][dc + 1] =
                (yy >= 0 && yy < H_ && xc >= 0 && xc < W_) ? mb[yy * W_ + xc] : 0.f;
        }

    // gradient gating term (low-res, shared by all 4 subpixels)
    float g[9];
    float mc = m[1][1];
#pragma unroll
    for (int k = 0; k < 9; k++) {
        float d = m[k / 3][k % 3] - mc;
        g[k] = 1.0f / (d * d + 1.0f);
    }

    float* wkp = wk + (size_t)idx * 36;
#pragma unroll
    for (int i = 0; i < 2; i++)
#pragma unroll
        for (int j = 0; j < 2; j++) {
            // 5x5 conv at hi-res pixel (2y+i, 2x+j); tap (p,q) reads
            // mean_up[2y+i+p-2, 2x+j+q-2] = m[(i+p-2)>>1 +1][(j+q-2)>>1 +1]
            // (zero padding at hi-res bounds == low-res bounds, checked)
            float o0 = 0.f, o1 = 0.f;
#pragma unroll
            for (int p = 0; p < 5; p++)
#pragma unroll
                for (int q = 0; q < 5; q++) {
                    int dr = (i + p - 2) >> 1;   // arithmetic shift = floor div
                    int dc = (j + q - 2) >> 1;
                    float v = m[dr + 1][dc + 1];
                    o0 = fmaf(v, sw[p * 5 + q], o0);
                    o1 = fmaf(v, sw[25 + p * 5 + q], o1);
                }
            float s0 = (i ? 0.25f : -0.25f) + 0.25f * tanhf(o0 + sb[0]);
            float s1 = (j ? 0.25f : -0.25f) + 0.25f * tanhf(o1 + sb[1]);

            float l[9];
            float mx = -1e30f;
#pragma unroll
            for (int k = 0; k < 9; k++) {
                float d0 = s0 - (float)(k / 3 - 1);
                float d1 = s1 - (float)(k % 3 - 1);
                float ker = 1.0f / (d0 * d0 + d1 * d1 + 0.5f);
                l[k] = g[k] * ker;
                mx = fmaxf(mx, l[k]);
            }
            float sum = 0.f;
#pragma unroll
            for (int k = 0; k < 9; k++) { l[k] = expf(l[k] - mx); sum += l[k]; }
            float inv = 1.0f / sum;
#pragma unroll
            for (int k = 0; k < 9; k++) wkp[(i * 2 + j) * 9 + k] = l[k] * inv;
        }
}

// ---------------------------------------------------------------------------
// K3: CARAFE apply. Block = (b,y) row, thread = x. Weights (36f) live in
// registers across the full channel loop; per channel: 9 x-loads (L1-shared
// with neighbor threads), 36 FMAs, 2x float2 coalesced stores.
// ---------------------------------------------------------------------------
__global__ void __launch_bounds__(128) carafe_kernel(const float* __restrict__ x,
                                                     const float* __restrict__ wk,
                                                     float* __restrict__ out)
{
    int by = blockIdx.x;            // b*128 + y
    int b = by >> 7, y = by & 127;
    int xx = threadIdx.x;           // 0..127

    float w[36];
    const float4* wp = (const float4*)(wk + ((size_t)(by * W_ + xx)) * 36);
#pragma unroll
    for (int t = 0; t < 9; t++) {
        float4 v = wp[t];
        w[4 * t + 0] = v.x; w[4 * t + 1] = v.y;
        w[4 * t + 2] = v.z; w[4 * t + 3] = v.w;
    }

    const float* xb = x + ((size_t)b << 20) + y * W_ + xx;
    float* ob = out + (size_t)b * C_ * (HS * WS) + (size_t)(2 * y) * WS + 2 * xx;

    bool tN = (y > 0), tS = (y < H_ - 1), tW = (xx > 0), tE = (xx < W_ - 1);

    for (int c = 0; c < C_; c++) {
        const float* p = xb + ((size_t)c << 14);
        float v[9];
        v[0] = (tN && tW) ? p[-W_ - 1] : 0.f;
        v[1] = tN ? p[-W_] : 0.f;
        v[2] = (tN && tE) ? p[-W_ + 1] : 0.f;
        v[3] = tW ? p[-1] : 0.f;
        v[4] = p[0];
        v[5] = tE ? p[1] : 0.f;
        v[6] = (tS && tW) ? p[W_ - 1] : 0.f;
        v[7] = tS ? p[W_] : 0.f;
        v[8] = (tS && tE) ? p[W_ + 1] : 0.f;

        float a = 0.f, bq = 0.f, cq = 0.f, d = 0.f;
#pragma unroll
        for (int k = 0; k < 9; k++) {
            a  = fmaf(w[k],      v[k], a);   // sub (0,0)
            bq = fmaf(w[9 + k],  v[k], bq);  // sub (0,1)
            cq = fmaf(w[18 + k], v[k], cq);  // sub (1,0)
            d  = fmaf(w[27 + k], v[k], d);   // sub (1,1)
        }
        float* orow = ob + (size_t)c * (HS * WS);
        *(float2*)orow          = make_float2(a, bq);
        *(float2*)(orow + WS)   = make_float2(cq, d);
    }
}

extern "C" void kernel_launch(void* const* d_in, const int* in_sizes, int n_in,
                              void* d_out, int out_size)
{
    const float* x     = (const float*)d_in[0];   // [8,64,128,128]
    const float* w_off = (const float*)d_in[1];   // [2,1,5,5]
    const float* b_off = (const float*)d_in[2];   // [2]
    float* out = (float*)d_out;                   // [8,64,256,256]

    float* mean;
    float* wk;
    cudaGetSymbolAddress((void**)&mean, g_mean);
    cudaGetSymbolAddress((void**)&wk, g_wk);

    const int NP = B_ * H_ * W_;   // 131072
    mean_kernel<<<(NP + 255) / 256, 256>>>(x, mean);
    weights_kernel<<<(NP + 255) / 256, 256>>>(mean, w_off, b_off, wk);
    carafe_kernel<<<B_ * H_, 128>>>(x, wk, out);
}

// round 3
// speedup vs baseline: 1.0057x; 1.0057x over previous
#include <cuda_runtime.h>
#include <cuda_bf16.h>
#include <math.h>

#define B_ 8
#define C_ 64
#define H_ 128
#define W_ 128
#define HS 256
#define WS 256
#define NP (B_ * H_ * W_)   // 131072

// Scratch: 4 partial channel-sums + final mean
__device__ float g_meanp[4 * NP];
__device__ float g_mean[NP];

// ---------------------------------------------------------------------------
// K1a: partial channel sums (16 channels per thread, 4x parallelism => full
// chip occupancy; every load coalesced 128B per warp per channel).
// ---------------------------------------------------------------------------
__global__ void mean_partial_kernel(const float* __restrict__ x,
                                    float* __restrict__ mp)
{
    int t = blockIdx.x * blockDim.x + threadIdx.x;   // 4*NP threads
    int cg  = t >> 17;           // channel group 0..3
    int idx = t & (NP - 1);
    int b = idx >> 14;
    int p = idx & 16383;
    const float* px = x + ((size_t)b << 20) + ((size_t)(cg * 16) << 14) + p;
    float s = 0.f;
#pragma unroll
    for (int c = 0; c < 16; c++) s += px[(size_t)c << 14];
    mp[t] = s;
}

// K1b: tiny reduce of 4 partials -> mean
__global__ void mean_reduce_kernel(const float* __restrict__ mp,
                                   float* __restrict__ mean)
{
    int idx = blockIdx.x * blockDim.x + threadIdx.x;
    if (idx >= NP) return;
    mean[idx] = (mp[idx] + mp[NP + idx] + mp[2 * NP + idx] + mp[3 * NP + idx])
                * (1.0f / 64.0f);
}

// ---------------------------------------------------------------------------
// K2 (fused): per-thread weight computation (registers only) + CARAFE apply.
// Block = (b,y), thread = x. No weights intermediate in memory at all.
// ---------------------------------------------------------------------------
__global__ void __launch_bounds__(128) carafe_fused_kernel(
    const float* __restrict__ x,
    const float* __restrict__ mean,
    const float* __restrict__ w_off,
    const float* __restrict__ b_off,
    float* __restrict__ out)
{
    __shared__ float sw[50];
    __shared__ float sb[2];
    if (threadIdx.x < 50) sw[threadIdx.x] = w_off[threadIdx.x];
    if (threadIdx.x < 2)  sb[threadIdx.x] = b_off[threadIdx.x];
    __syncthreads();

    int by = blockIdx.x;            // b*128 + y
    int b = by >> 7, y = by & 127;
    int xx = threadIdx.x;           // 0..127

    // ---- load 3x3 mean neighborhood (zero-padded) ----
    const float* mb = mean + ((size_t)b << 14);
    float m[3][3];
#pragma unroll
    for (int dr = -1; dr <= 1; dr++)
#pragma unroll
        for (int dc = -1; dc <= 1; dc++) {
            int yy = y + dr, xc = xx + dc;
            m[dr + 1][dc + 1] =
                (yy >= 0 && yy < H_ && xc >= 0 && xc < W_) ? mb[yy * W_ + xc] : 0.f;
        }

    // ---- gradient gating (shared by 4 subpixels) ----
    float g[9];
    float mc = m[1][1];
#pragma unroll
    for (int k = 0; k < 9; k++) {
        float d = m[k / 3][k % 3] - mc;
        g[k] = 1.0f / (d * d + 1.0f);
    }

    // ---- per-subpixel softmaxed reassembly weights -> registers ----
    float w[36];
#pragma unroll
    for (int i = 0; i < 2; i++)
#pragma unroll
        for (int j = 0; j < 2; j++) {
            // 5x5 conv on nearest-up(mean) collapses to 3x3 low-res taps
            float o0 = 0.f, o1 = 0.f;
#pragma unroll
            for (int p = 0; p < 5; p++)
#pragma unroll
                for (int q = 0; q < 5; q++) {
                    int dr = (i + p - 2) >> 1;   // floor div by 2
                    int dc = (j + q - 2) >> 1;
                    float v = m[dr + 1][dc + 1];
                    o0 = fmaf(v, sw[p * 5 + q], o0);
                    o1 = fmaf(v, sw[25 + p * 5 + q], o1);
                }
            float s0 = (i ? 0.25f : -0.25f) + 0.25f * tanhf(o0 + sb[0]);
            float s1 = (j ? 0.25f : -0.25f) + 0.25f * tanhf(o1 + sb[1]);

            float l[9];
            float mx = -1e30f;
#pragma unroll
            for (int k = 0; k < 9; k++) {
                float d0 = s0 - (float)(k / 3 - 1);
                float d1 = s1 - (float)(k % 3 - 1);
                float ker = 1.0f / (d0 * d0 + d1 * d1 + 0.5f);
                l[k] = g[k] * ker;
                mx = fmaxf(mx, l[k]);
            }
            float sum = 0.f;
#pragma unroll
            for (int k = 0; k < 9; k++) { l[k] = expf(l[k] - mx); sum += l[k]; }
            float inv = 1.0f / sum;
#pragma unroll
            for (int k = 0; k < 9; k++) w[(i * 2 + j) * 9 + k] = l[k] * inv;
        }

    // ---- CARAFE channel loop ----
    const float* xb = x + ((size_t)b << 20) + y * W_ + xx;
    float* ob = out + (size_t)b * C_ * (HS * WS) + (size_t)(2 * y) * WS + 2 * xx;

    bool tN = (y > 0), tS = (y < H_ - 1), tW = (xx > 0), tE = (xx < W_ - 1);

#pragma unroll 4
    for (int c = 0; c < C_; c++) {
        const float* p = xb + ((size_t)c << 14);
        float v[9];
        v[0] = (tN && tW) ? p[-W_ - 1] : 0.f;
        v[1] = tN ? p[-W_] : 0.f;
        v[2] = (tN && tE) ? p[-W_ + 1] : 0.f;
        v[3] = tW ? p[-1] : 0.f;
        v[4] = p[0];
        v[5] = tE ? p[1] : 0.f;
        v[6] = (tS && tW) ? p[W_ - 1] : 0.f;
        v[7] = tS ? p[W_] : 0.f;
        v[8] = (tS && tE) ? p[W_ + 1] : 0.f;

        float a = 0.f, bq = 0.f, cq = 0.f, d = 0.f;
#pragma unroll
        for (int k = 0; k < 9; k++) {
            a  = fmaf(w[k],      v[k], a);   // sub (0,0)
            bq = fmaf(w[9 + k],  v[k], bq);  // sub (0,1)
            cq = fmaf(w[18 + k], v[k], cq);  // sub (1,0)
            d  = fmaf(w[27 + k], v[k], d);   // sub (1,1)
        }
        float* orow = ob + (size_t)c * (HS * WS);
        *(float2*)orow        = make_float2(a, bq);
        *(float2*)(orow + WS) = make_float2(cq, d);
    }
}

extern "C" void kernel_launch(void* const* d_in, const int* in_sizes, int n_in,
                              void* d_out, int out_size)
{
    const float* x     = (const float*)d_in[0];   // [8,64,128,128]
    const float* w_off = (const float*)d_in[1];   // [2,1,5,5]
    const float* b_off = (const float*)d_in[2];   // [2]
    float* out = (float*)d_out;                   // [8,64,256,256]

    float* mp;
    float* mean;
    cudaGetSymbolAddress((void**)&mp, g_meanp);
    cudaGetSymbolAddress((void**)&mean, g_mean);

    mean_partial_kernel<<<(4 * NP) / 256, 256>>>(x, mp);
    mean_reduce_kernel<<<NP / 256, 256>>>(mp, mean);
    carafe_fused_kernel<<<B_ * H_, 128>>>(x, mean, w_off, b_off, out);
}

// round 4
// speedup vs baseline: 1.3755x; 1.3677x over previous
#include <cuda_runtime.h>
#include <cuda_bf16.h>
#include <math.h>

#define B_ 8
#define C_ 64
#define H_ 128
#define W_ 128
#define HS 256
#define WS 256
#define NP (B_ * H_ * W_)      // 131072
#define NP4 (NP / 4)           // 32768
#define CH_SPLIT 2             // channels per carafe block = 32
#define CPB (C_ / CH_SPLIT)

__device__ float g_meanp[4 * NP];
__device__ float g_mean[NP];

// ---------------------------------------------------------------------------
// K1a: partial channel sums, float4 over x-dim. 4 channel groups x 32768 f4.
// ---------------------------------------------------------------------------
__global__ void mean_partial_kernel(const float* __restrict__ x,
                                    float4* __restrict__ mp4)
{
    int t = blockIdx.x * blockDim.x + threadIdx.x;   // 4*NP4 threads
    int cg   = t >> 15;
    int idx4 = t & (NP4 - 1);
    int b  = idx4 >> 12;          // 4096 float4 per image-plane
    int p4 = idx4 & 4095;
    const float4* px = (const float4*)(x + ((size_t)b << 20) + ((size_t)(cg * 16) << 14)) + p4;
    float4 s = make_float4(0.f, 0.f, 0.f, 0.f);
#pragma unroll
    for (int c = 0; c < 16; c++) {
        float4 v = px[(size_t)c << 12];
        s.x += v.x; s.y += v.y; s.z += v.z; s.w += v.w;
    }
    mp4[t] = s;
}

__global__ void mean_reduce_kernel(const float4* __restrict__ mp4,
                                   float4* __restrict__ mean4)
{
    int i = blockIdx.x * blockDim.x + threadIdx.x;
    if (i >= NP4) return;
    float4 a = mp4[i], b = mp4[NP4 + i], c = mp4[2 * NP4 + i], d = mp4[3 * NP4 + i];
    mean4[i] = make_float4((a.x + b.x + c.x + d.x) * (1.f / 64.f),
                           (a.y + b.y + c.y + d.y) * (1.f / 64.f),
                           (a.z + b.z + c.z + d.z) * (1.f / 64.f),
                           (a.w + b.w + c.w + d.w) * (1.f / 64.f));
}

// ---------------------------------------------------------------------------
// K2: fused weights + CARAFE. Warp = one full low-res row (4 cols/lane).
// Seam taps via shuffle; warp edges == image edges (zero pad).
// Block = 4 warps = 4 rows; grid splits the channel loop CH_SPLIT ways.
// ---------------------------------------------------------------------------
__device__ __forceinline__ float4 ldg4_or_zero(const float* p, bool pred)
{
    if (pred) return *(const float4*)p;
    return make_float4(0.f, 0.f, 0.f, 0.f);
}

__global__ void __launch_bounds__(128) carafe_fused_kernel(
    const float* __restrict__ x,
    const float* __restrict__ mean,
    const float* __restrict__ w_off,
    const float* __restrict__ b_off,
    float* __restrict__ out)
{
    __shared__ float sw[50];
    __shared__ float sb[2];
    if (threadIdx.x < 50) sw[threadIdx.x] = w_off[threadIdx.x];
    if (threadIdx.x < 2)  sb[threadIdx.x] = b_off[threadIdx.x];
    __syncthreads();

    int rb = blockIdx.x >> 1;            // row-group 0..255
    int cs = blockIdx.x & 1;             // channel half
    int warp = threadIdx.x >> 5;
    int lane = threadIdx.x & 31;
    int by = rb * 4 + warp;              // 0..1023
    int b = by >> 7, y = by & 127;

    bool hasN = (y > 0), hasS = (y < H_ - 1);

    // ---- mean neighborhood rows as [3][6]: {left, 4 own cols, right} ----
    const float* mb = mean + ((size_t)b << 14);
    float mm[3][6];
#pragma unroll
    for (int r = 0; r < 3; r++) {
        int yy = y - 1 + r;
        bool ok = (yy >= 0 && yy < H_);
        float4 q = ldg4_or_zero(mb + yy * W_ + 4 * lane, ok);
        float l = __shfl_up_sync(0xffffffffu, q.w, 1);
        float rr = __shfl_down_sync(0xffffffffu, q.x, 1);
        mm[r][0] = (lane == 0) ? 0.f : l;
        mm[r][1] = q.x; mm[r][2] = q.y; mm[r][3] = q.z; mm[r][4] = q.w;
        mm[r][5] = (lane == 31) ? 0.f : rr;
    }

    // ---- per-pixel weights: w[p][s][k], p=0..3 pixels, s=0..3 sub, k=0..8 ----
    float w[144];
#pragma unroll
    for (int p = 0; p < 4; p++) {
        // 3x3 mean taps for this pixel
        float m0[3][3];
#pragma unroll
        for (int r = 0; r < 3; r++) {
            m0[r][0] = mm[r][p]; m0[r][1] = mm[r][p + 1]; m0[r][2] = mm[r][p + 2];
        }
        float g[9];
        float mc = m0[1][1];
#pragma unroll
        for (int k = 0; k < 9; k++) {
            float d = m0[k / 3][k % 3] - mc;
            g[k] = __fdividef(1.0f, d * d + 1.0f);
        }
#pragma unroll
        for (int i = 0; i < 2; i++)
#pragma unroll
            for (int j = 0; j < 2; j++) {
                float o0 = 0.f, o1 = 0.f;
#pragma unroll
                for (int pp = 0; pp < 5; pp++)
#pragma unroll
                    for (int qq = 0; qq < 5; qq++) {
                        int dr = (i + pp - 2) >> 1;
                        int dc = (j + qq - 2) >> 1;
                        float v = m0[dr + 1][dc + 1];
                        o0 = fmaf(v, sw[pp * 5 + qq], o0);
                        o1 = fmaf(v, sw[25 + pp * 5 + qq], o1);
                    }
                float s0 = (i ? 0.25f : -0.25f) + 0.25f * tanhf(o0 + sb[0]);
                float s1 = (j ? 0.25f : -0.25f) + 0.25f * tanhf(o1 + sb[1]);

                float l[9];
                float sum = 0.f;
#pragma unroll
                for (int k = 0; k < 9; k++) {
                    float d0 = s0 - (float)(k / 3 - 1);
                    float d1 = s1 - (float)(k % 3 - 1);
                    float ker = __fdividef(1.0f, d0 * d0 + d1 * d1 + 0.5f);
                    // values bounded in (0,2]: no max-subtraction needed
                    l[k] = __expf(g[k] * ker);
                    sum += l[k];
                }
                float inv = __fdividef(1.0f, sum);
#pragma unroll
                for (int k = 0; k < 9; k++)
                    w[(p * 4 + (i * 2 + j)) * 9 + k] = l[k] * inv;
            }
    }

    // ---- CARAFE channel loop ----
    const float* xb = x + ((size_t)b << 20) + ((size_t)(cs * CPB) << 14)
                        + y * W_ + 4 * lane;
    float* ob = out + (size_t)b * C_ * (HS * WS) + (size_t)(cs * CPB) * (HS * WS)
                    + (size_t)(2 * y) * WS + 8 * lane;

#pragma unroll 2
    for (int c = 0; c < CPB; c++) {
        const float* p0 = xb + ((size_t)c << 14);
        float vv[3][6];
        {
            float4 q0 = ldg4_or_zero(p0 - W_, hasN);
            float4 q1 = *(const float4*)p0;
            float4 q2 = ldg4_or_zero(p0 + W_, hasS);
            float l0 = __shfl_up_sync(0xffffffffu, q0.w, 1);
            float l1 = __shfl_up_sync(0xffffffffu, q1.w, 1);
            float l2 = __shfl_up_sync(0xffffffffu, q2.w, 1);
            float r0 = __shfl_down_sync(0xffffffffu, q0.x, 1);
            float r1 = __shfl_down_sync(0xffffffffu, q1.x, 1);
            float r2 = __shfl_down_sync(0xffffffffu, q2.x, 1);
            bool z0 = (lane == 0), z31 = (lane == 31);
            vv[0][0] = z0 ? 0.f : l0; vv[1][0] = z0 ? 0.f : l1; vv[2][0] = z0 ? 0.f : l2;
            vv[0][1] = q0.x; vv[0][2] = q0.y; vv[0][3] = q0.z; vv[0][4] = q0.w;
            vv[1][1] = q1.x; vv[1][2] = q1.y; vv[1][3] = q1.z; vv[1][4] = q1.w;
            vv[2][1] = q2.x; vv[2][2] = q2.y; vv[2][3] = q2.z; vv[2][4] = q2.w;
            vv[0][5] = z31 ? 0.f : r0; vv[1][5] = z31 ? 0.f : r1; vv[2][5] = z31 ? 0.f : r2;
        }

        float o0[8], o1[8];
#pragma unroll
        for (int p = 0; p < 4; p++) {
            float a = 0.f, bq = 0.f, cq = 0.f, d = 0.f;
#pragma unroll
            for (int r = 0; r < 3; r++)
#pragma unroll
                for (int cc = 0; cc < 3; cc++) {
                    int k = r * 3 + cc;
                    float tv = vv[r][p + cc];
                    a  = fmaf(w[(p * 4 + 0) * 9 + k], tv, a);
                    bq = fmaf(w[(p * 4 + 1) * 9 + k], tv, bq);
                    cq = fmaf(w[(p * 4 + 2) * 9 + k], tv, cq);
                    d  = fmaf(w[(p * 4 + 3) * 9 + k], tv, d);
                }
            o0[2 * p] = a;  o0[2 * p + 1] = bq;
            o1[2 * p] = cq; o1[2 * p + 1] = d;
        }

        float* orow = ob + (size_t)c * (HS * WS);
        *(float4*)(orow)          = make_float4(o0[0], o0[1], o0[2], o0[3]);
        *(float4*)(orow + 4)      = make_float4(o0[4], o0[5], o0[6], o0[7]);
        *(float4*)(orow + WS)     = make_float4(o1[0], o1[1], o1[2], o1[3]);
        *(float4*)(orow + WS + 4) = make_float4(o1[4], o1[5], o1[6], o1[7]);
    }
}

extern "C" void kernel_launch(void* const* d_in, const int* in_sizes, int n_in,
                              void* d_out, int out_size)
{
    const float* x     = (const float*)d_in[0];   // [8,64,128,128]
    const float* w_off = (const float*)d_in[1];   // [2,1,5,5]
    const float* b_off = (const float*)d_in[2];   // [2]
    float* out = (float*)d_out;                   // [8,64,256,256]

    float* mp;
    float* mean;
    cudaGetSymbolAddress((void**)&mp, g_meanp);
    cudaGetSymbolAddress((void**)&mean, g_mean);

    mean_partial_kernel<<<(4 * NP4) / 256, 256>>>(x, (float4*)mp);
    mean_reduce_kernel<<<NP4 / 256, 256>>>((const float4*)mp, (float4*)mean);
    carafe_fused_kernel<<<(B_ * H_ / 4) * CH_SPLIT, 128>>>(x, mean, w_off, b_off, out);
}

// round 5
// speedup vs baseline: 1.4394x; 1.0465x over previous
#include <cuda_runtime.h>
#include <cuda_bf16.h>
#include <math.h>

#define B_ 8
#define C_ 64
#define H_ 128
#define W_ 128
#define HS 256
#define WS 256
#define NP (B_ * H_ * W_)      // 131072
#define NP4 (NP / 4)           // 32768
#define CH_SPLIT 2
#define CPB (C_ / CH_SPLIT)    // 32

__device__ float g_meanp[8 * NP];
__device__ float g_mean[NP];

// ---------------------------------------------------------------------------
// K1a: partial channel sums. 8 channel groups x 8 channels -> 262K threads.
// ---------------------------------------------------------------------------
__global__ void mean_partial_kernel(const float* __restrict__ x,
                                    float4* __restrict__ mp4)
{
    int t = blockIdx.x * blockDim.x + threadIdx.x;   // 8*NP4 threads
    int cg   = t >> 15;          // 0..7
    int idx4 = t & (NP4 - 1);
    int b  = idx4 >> 12;
    int p4 = idx4 & 4095;
    const float4* px = (const float4*)(x + ((size_t)b << 20) + ((size_t)(cg * 8) << 14)) + p4;
    float4 s = make_float4(0.f, 0.f, 0.f, 0.f);
#pragma unroll
    for (int c = 0; c < 8; c++) {
        float4 v = px[(size_t)c << 12];
        s.x += v.x; s.y += v.y; s.z += v.z; s.w += v.w;
    }
    mp4[t] = s;
}

__global__ void mean_reduce_kernel(const float4* __restrict__ mp4,
                                   float4* __restrict__ mean4)
{
    int i = blockIdx.x * blockDim.x + threadIdx.x;
    if (i >= NP4) return;
    float sx = 0.f, sy = 0.f, sz = 0.f, sw_ = 0.f;
#pragma unroll
    for (int g = 0; g < 8; g++) {
        float4 v = mp4[g * NP4 + i];
        sx += v.x; sy += v.y; sz += v.z; sw_ += v.w;
    }
    mean4[i] = make_float4(sx * (1.f / 64.f), sy * (1.f / 64.f),
                           sz * (1.f / 64.f), sw_ * (1.f / 64.f));
}

// ---------------------------------------------------------------------------
// K2: fused weights + CARAFE. Warp = full low-res row (4 cols/lane).
// Warp pair splits the two hi-res output sub-rows (i=0 / i=1):
// 72 weight regs per thread -> <=128 regs -> 2 CTAs(256thr)/SM resident.
// ---------------------------------------------------------------------------
__device__ __forceinline__ float4 ldg4_or_zero(const float* p, bool pred)
{
    if (pred) return *(const float4*)p;
    return make_float4(0.f, 0.f, 0.f, 0.f);
}

__global__ void __launch_bounds__(256, 2) carafe_fused_kernel(
    const float* __restrict__ x,
    const float* __restrict__ mean,
    const float* __restrict__ w_off,
    const float* __restrict__ b_off,
    float* __restrict__ out)
{
    __shared__ float sw[50];
    __shared__ float sb[2];
    if (threadIdx.x < 50) sw[threadIdx.x] = w_off[threadIdx.x];
    if (threadIdx.x < 2)  sb[threadIdx.x] = b_off[threadIdx.x];
    __syncthreads();

    int rb = blockIdx.x >> 1;            // row-group 0..255
    int cs = blockIdx.x & 1;             // channel half
    int warp = threadIdx.x >> 5;         // 0..7
    int lane = threadIdx.x & 31;
    int irow = warp >> 2;                // hi-res sub-row 0/1
    int by = rb * 4 + (warp & 3);        // 0..1023
    int b = by >> 7, y = by & 127;

    bool hasN = (y > 0), hasS = (y < H_ - 1);

    // ---- mean neighborhood rows [3][6]: {left halo, 4 own, right halo} ----
    const float* mb = mean + ((size_t)b << 14);
    float mm[3][6];
#pragma unroll
    for (int r = 0; r < 3; r++) {
        int yy = y - 1 + r;
        bool ok = (yy >= 0 && yy < H_);
        float4 q = ldg4_or_zero(mb + yy * W_ + 4 * lane, ok);
        float l = __shfl_up_sync(0xffffffffu, q.w, 1);
        float rr = __shfl_down_sync(0xffffffffu, q.x, 1);
        mm[r][0] = (lane == 0) ? 0.f : l;
        mm[r][1] = q.x; mm[r][2] = q.y; mm[r][3] = q.z; mm[r][4] = q.w;
        mm[r][5] = (lane == 31) ? 0.f : rr;
    }

    // ---- weights: w[p][j][k], p=0..3 pixels, j=0..1 subcols, fixed i=irow ----
    float w[72];
#pragma unroll
    for (int p = 0; p < 4; p++) {
        float m0[3][3];
#pragma unroll
        for (int r = 0; r < 3; r++) {
            m0[r][0] = mm[r][p]; m0[r][1] = mm[r][p + 1]; m0[r][2] = mm[r][p + 2];
        }
        float g[9];
        float mc = m0[1][1];
#pragma unroll
        for (int k = 0; k < 9; k++) {
            float d = m0[k / 3][k % 3] - mc;
            g[k] = __fdividef(1.0f, d * d + 1.0f);
        }
#pragma unroll
        for (int j = 0; j < 2; j++) {
            float o0 = 0.f, o1 = 0.f;
#pragma unroll
            for (int pp = 0; pp < 5; pp++)
#pragma unroll
                for (int qq = 0; qq < 5; qq++) {
                    int dr = (irow + pp - 2) >> 1;
                    int dc = (j + qq - 2) >> 1;
                    float v = m0[dr + 1][dc + 1];
                    o0 = fmaf(v, sw[pp * 5 + qq], o0);
                    o1 = fmaf(v, sw[25 + pp * 5 + qq], o1);
                }
            float s0 = (irow ? 0.25f : -0.25f) + 0.25f * tanhf(o0 + sb[0]);
            float s1 = (j ? 0.25f : -0.25f) + 0.25f * tanhf(o1 + sb[1]);

            float l[9];
            float sum = 0.f;
#pragma unroll
            for (int k = 0; k < 9; k++) {
                float d0 = s0 - (float)(k / 3 - 1);
                float d1 = s1 - (float)(k % 3 - 1);
                float ker = __fdividef(1.0f, d0 * d0 + d1 * d1 + 0.5f);
                l[k] = __expf(g[k] * ker);   // arg in (0,2]: no max-sub needed
                sum += l[k];
            }
            float inv = __fdividef(1.0f, sum);
#pragma unroll
            for (int k = 0; k < 9; k++)
                w[(p * 2 + j) * 9 + k] = l[k] * inv;
        }
    }

    // ---- CARAFE channel loop: this warp writes hi-res row 2y+irow only ----
    const float* xb = x + ((size_t)b << 20) + ((size_t)(cs * CPB) << 14)
                        + y * W_ + 4 * lane;
    float* ob = out + (size_t)b * C_ * (HS * WS) + (size_t)(cs * CPB) * (HS * WS)
                    + (size_t)(2 * y + irow) * WS + 8 * lane;

#pragma unroll 2
    for (int c = 0; c < CPB; c++) {
        const float* p0 = xb + ((size_t)c << 14);
        float vv[3][6];
        {
            float4 q0 = ldg4_or_zero(p0 - W_, hasN);
            float4 q1 = *(const float4*)p0;
            float4 q2 = ldg4_or_zero(p0 + W_, hasS);
            float l0 = __shfl_up_sync(0xffffffffu, q0.w, 1);
            float l1 = __shfl_up_sync(0xffffffffu, q1.w, 1);
            float l2 = __shfl_up_sync(0xffffffffu, q2.w, 1);
            float r0 = __shfl_down_sync(0xffffffffu, q0.x, 1);
            float r1 = __shfl_down_sync(0xffffffffu, q1.x, 1);
            float r2 = __shfl_down_sync(0xffffffffu, q2.x, 1);
            bool z0 = (lane == 0), z31 = (lane == 31);
            vv[0][0] = z0 ? 0.f : l0; vv[1][0] = z0 ? 0.f : l1; vv[2][0] = z0 ? 0.f : l2;
            vv[0][1] = q0.x; vv[0][2] = q0.y; vv[0][3] = q0.z; vv[0][4] = q0.w;
            vv[1][1] = q1.x; vv[1][2] = q1.y; vv[1][3] = q1.z; vv[1][4] = q1.w;
            vv[2][1] = q2.x; vv[2][2] = q2.y; vv[2][3] = q2.z; vv[2][4] = q2.w;
            vv[0][5] = z31 ? 0.f : r0; vv[1][5] = z31 ? 0.f : r1; vv[2][5] = z31 ? 0.f : r2;
        }

        float o[8];
#pragma unroll
        for (int p = 0; p < 4; p++) {
            float a = 0.f, bq = 0.f;
#pragma unroll
            for (int r = 0; r < 3; r++)
#pragma unroll
                for (int cc = 0; cc < 3; cc++) {
                    int k = r * 3 + cc;
                    float tv = vv[r][p + cc];
                    a  = fmaf(w[(p * 2 + 0) * 9 + k], tv, a);
                    bq = fmaf(w[(p * 2 + 1) * 9 + k], tv, bq);
                }
            o[2 * p] = a; o[2 * p + 1] = bq;
        }

        float* orow = ob + (size_t)c * (HS * WS);
        *(float4*)(orow)     = make_float4(o[0], o[1], o[2], o[3]);
        *(float4*)(orow + 4) = make_float4(o[4], o[5], o[6], o[7]);
    }
}

extern "C" void kernel_launch(void* const* d_in, const int* in_sizes, int n_in,
                              void* d_out, int out_size)
{
    const float* x     = (const float*)d_in[0];   // [8,64,128,128]
    const float* w_off = (const float*)d_in[1];   // [2,1,5,5]
    const float* b_off = (const float*)d_in[2];   // [2]
    float* out = (float*)d_out;                   // [8,64,256,256]

    float* mp;
    float* mean;
    cudaGetSymbolAddress((void**)&mp, g_meanp);
    cudaGetSymbolAddress((void**)&mean, g_mean);

    mean_partial_kernel<<<(8 * NP4) / 256, 256>>>(x, (float4*)mp);
    mean_reduce_kernel<<<NP4 / 256, 256>>>((const float4*)mp, (float4*)mean);
    carafe_fused_kernel<<<(B_ * H_ / 4) * CH_SPLIT, 256>>>(x, mean, w_off, b_off, out);
}

// round 6
// speedup vs baseline: 1.5720x; 1.0921x over previous
#include <cuda_runtime.h>
#include <cuda_bf16.h>
#include <math.h>

#define B_ 8
#define C_ 64
#define H_ 128
#define W_ 128
#define HS 256
#define WS 256
#define NP (B_ * H_ * W_)      // 131072
#define NP4 (NP / 4)           // 32768

__device__ float g_meanp[8 * NP];
__device__ float g_mean[NP];

// ---------------------------------------------------------------------------
// packed f32x2 helpers (Blackwell)
// ---------------------------------------------------------------------------
__device__ __forceinline__ unsigned long long pack2(float lo, float hi)
{
    unsigned long long r;
    asm("mov.b64 %0, {%1, %2};" : "=l"(r) : "f"(lo), "f"(hi));
    return r;
}
__device__ __forceinline__ float2 unpack2(unsigned long long v)
{
    float lo, hi;
    asm("mov.b64 {%0, %1}, %2;" : "=f"(lo), "=f"(hi) : "l"(v));
    return make_float2(lo, hi);
}
#define FMA2(acc, ww, tt) \
    asm("fma.rn.f32x2 %0, %1, %2, %0;" : "+l"(acc) : "l"(ww), "l"(tt))

// ---------------------------------------------------------------------------
// K1a: partial channel sums. 8 channel groups x 8 channels.
// ---------------------------------------------------------------------------
__global__ void mean_partial_kernel(const float* __restrict__ x,
                                    float4* __restrict__ mp4)
{
    int t = blockIdx.x * blockDim.x + threadIdx.x;   // 8*NP4 threads
    int cg   = t >> 15;          // 0..7
    int idx4 = t & (NP4 - 1);
    int b  = idx4 >> 12;
    int p4 = idx4 & 4095;
    const float4* px = (const float4*)(x + ((size_t)b << 20) + ((size_t)(cg * 8) << 14)) + p4;
    float4 s = make_float4(0.f, 0.f, 0.f, 0.f);
#pragma unroll
    for (int c = 0; c < 8; c++) {
        float4 v = px[(size_t)c << 12];
        s.x += v.x; s.y += v.y; s.z += v.z; s.w += v.w;
    }
    mp4[t] = s;
}

__global__ void mean_reduce_kernel(const float4* __restrict__ mp4,
                                   float4* __restrict__ mean4)
{
    int i = blockIdx.x * blockDim.x + threadIdx.x;
    if (i >= NP4) return;
    float sx = 0.f, sy = 0.f, sz = 0.f, sw_ = 0.f;
#pragma unroll
    for (int g = 0; g < 8; g++) {
        float4 v = mp4[g * NP4 + i];
        sx += v.x; sy += v.y; sz += v.z; sw_ += v.w;
    }
    mean4[i] = make_float4(sx * (1.f / 64.f), sy * (1.f / 64.f),
                           sz * (1.f / 64.f), sw_ * (1.f / 64.f));
}

// ---------------------------------------------------------------------------
// K2: fused weights + CARAFE.
// Block = 128 thr = 4 warps = 2 low-res rows x 2 hi-res sub-rows.
// Warp = full low-res row, 4 cols/lane, halos via shuffle.
// All 64 channels per block (x read once); out stored with __stcs so the
// 134MB store stream doesn't evict x from L2.
// Inner product uses packed fma.rn.f32x2 over pixel pairs.
// ---------------------------------------------------------------------------
__device__ __forceinline__ float4 ldg4_or_zero(const float* p, bool pred)
{
    if (pred) return *(const float4*)p;
    return make_float4(0.f, 0.f, 0.f, 0.f);
}

__global__ void __launch_bounds__(128, 4) carafe_fused_kernel(
    const float* __restrict__ x,
    const float* __restrict__ mean,
    const float* __restrict__ w_off,
    const float* __restrict__ b_off,
    float* __restrict__ out)
{
    __shared__ float sw[50];
    __shared__ float sb[2];
    if (threadIdx.x < 50) sw[threadIdx.x] = w_off[threadIdx.x];
    if (threadIdx.x < 2)  sb[threadIdx.x] = b_off[threadIdx.x];
    __syncthreads();

    int warp = threadIdx.x >> 5;         // 0..3
    int lane = threadIdx.x & 31;
    int irow = warp >> 1;                // hi-res sub-row 0/1
    int by = blockIdx.x * 2 + (warp & 1);   // 0..1023
    int b = by >> 7, y = by & 127;

    bool hasN = (y > 0), hasS = (y < H_ - 1);

    // ---- mean neighborhood rows [3][6]: {left halo, 4 own, right halo} ----
    const float* mb = mean + ((size_t)b << 14);
    float mm[3][6];
#pragma unroll
    for (int r = 0; r < 3; r++) {
        int yy = y - 1 + r;
        bool ok = (yy >= 0 && yy < H_);
        float4 q = ldg4_or_zero(mb + yy * W_ + 4 * lane, ok);
        float l = __shfl_up_sync(0xffffffffu, q.w, 1);
        float rr = __shfl_down_sync(0xffffffffu, q.x, 1);
        mm[r][0] = (lane == 0) ? 0.f : l;
        mm[r][1] = q.x; mm[r][2] = q.y; mm[r][3] = q.z; mm[r][4] = q.w;
        mm[r][5] = (lane == 31) ? 0.f : rr;
    }

    // ---- weights, packed over pixel pairs: wp[pp*2+j][k] = {w_pix2pp, w_pix2pp+1}
    unsigned long long wp[4][9];
    {
        float lo[18];
#pragma unroll
        for (int p = 0; p < 4; p++) {
            float m0[3][3];
#pragma unroll
            for (int r = 0; r < 3; r++) {
                m0[r][0] = mm[r][p]; m0[r][1] = mm[r][p + 1]; m0[r][2] = mm[r][p + 2];
            }
            float g[9];
            float mc = m0[1][1];
#pragma unroll
            for (int k = 0; k < 9; k++) {
                float d = m0[k / 3][k % 3] - mc;
                g[k] = __fdividef(1.0f, d * d + 1.0f);
            }
            float cur[18];
#pragma unroll
            for (int j = 0; j < 2; j++) {
                float o0 = 0.f, o1 = 0.f;
#pragma unroll
                for (int pp = 0; pp < 5; pp++)
#pragma unroll
                    for (int qq = 0; qq < 5; qq++) {
                        int dr = (irow + pp - 2) >> 1;
                        int dc = (j + qq - 2) >> 1;
                        float v = m0[dr + 1][dc + 1];
                        o0 = fmaf(v, sw[pp * 5 + qq], o0);
                        o1 = fmaf(v, sw[25 + pp * 5 + qq], o1);
                    }
                float s0 = (irow ? 0.25f : -0.25f) + 0.25f * tanhf(o0 + sb[0]);
                float s1 = (j ? 0.25f : -0.25f) + 0.25f * tanhf(o1 + sb[1]);

                float l[9];
                float sum = 0.f;
#pragma unroll
                for (int k = 0; k < 9; k++) {
                    float d0 = s0 - (float)(k / 3 - 1);
                    float d1 = s1 - (float)(k % 3 - 1);
                    float ker = __fdividef(1.0f, d0 * d0 + d1 * d1 + 0.5f);
                    l[k] = __expf(g[k] * ker);   // arg in (0,2]: no max-sub needed
                    sum += l[k];
                }
                float inv = __fdividef(1.0f, sum);
#pragma unroll
                for (int k = 0; k < 9; k++) cur[j * 9 + k] = l[k] * inv;
            }
            if ((p & 1) == 0) {
#pragma unroll
                for (int t = 0; t < 18; t++) lo[t] = cur[t];
            } else {
#pragma unroll
                for (int j = 0; j < 2; j++)
#pragma unroll
                    for (int k = 0; k < 9; k++)
                        wp[(p >> 1) * 2 + j][k] = pack2(lo[j * 9 + k], cur[j * 9 + k]);
            }
        }
    }

    // ---- CARAFE channel loop: warp writes hi-res row 2y+irow, all 64 ch ----
    const float* xb = x + ((size_t)b << 20) + y * W_ + 4 * lane;
    float* ob = out + (size_t)b * C_ * (HS * WS)
                    + (size_t)(2 * y + irow) * WS + 8 * lane;

#pragma unroll 1
    for (int c = 0; c < C_; c++) {
        const float* p0 = xb + ((size_t)c << 14);
        float vv[3][6];
        {
            float4 q0 = ldg4_or_zero(p0 - W_, hasN);
            float4 q1 = *(const float4*)p0;
            float4 q2 = ldg4_or_zero(p0 + W_, hasS);
            float l0 = __shfl_up_sync(0xffffffffu, q0.w, 1);
            float l1 = __shfl_up_sync(0xffffffffu, q1.w, 1);
            float l2 = __shfl_up_sync(0xffffffffu, q2.w, 1);
            float r0 = __shfl_down_sync(0xffffffffu, q0.x, 1);
            float r1 = __shfl_down_sync(0xffffffffu, q1.x, 1);
            float r2 = __shfl_down_sync(0xffffffffu, q2.x, 1);
            bool z0 = (lane == 0), z31 = (lane == 31);
            vv[0][0] = z0 ? 0.f : l0; vv[1][0] = z0 ? 0.f : l1; vv[2][0] = z0 ? 0.f : l2;
            vv[0][1] = q0.x; vv[0][2] = q0.y; vv[0][3] = q0.z; vv[0][4] = q0.w;
            vv[1][1] = q1.x; vv[1][2] = q1.y; vv[1][3] = q1.z; vv[1][4] = q1.w;
            vv[2][1] = q2.x; vv[2][2] = q2.y; vv[2][3] = q2.z; vv[2][4] = q2.w;
            vv[0][5] = z31 ? 0.f : r0; vv[1][5] = z31 ? 0.f : r1; vv[2][5] = z31 ? 0.f : r2;
        }

        // packed tap pairs: tp[r][i] = {vv[r][i], vv[r][i+1]}
        unsigned long long tp[3][5];
#pragma unroll
        for (int r = 0; r < 3; r++)
#pragma unroll
            for (int i = 0; i < 5; i++)
                tp[r][i] = pack2(vv[r][i], vv[r][i + 1]);

        unsigned long long acc[2][2] = {{0ull, 0ull}, {0ull, 0ull}};
#pragma unroll
        for (int pp = 0; pp < 2; pp++)
#pragma unroll
            for (int r = 0; r < 3; r++)
#pragma unroll
                for (int cc = 0; cc < 3; cc++) {
                    int k = r * 3 + cc;
                    unsigned long long t = tp[r][2 * pp + cc];
                    FMA2(acc[pp][0], wp[pp * 2 + 0][k], t);
                    FMA2(acc[pp][1], wp[pp * 2 + 1][k], t);
                }

        float2 a00 = unpack2(acc[0][0]), a01 = unpack2(acc[0][1]);
        float2 a10 = unpack2(acc[1][0]), a11 = unpack2(acc[1][1]);

        float* orow = ob + (size_t)c * (HS * WS);
        __stcs((float4*)orow,       make_float4(a00.x, a01.x, a00.y, a01.y));
        __stcs((float4*)(orow + 4), make_float4(a10.x, a11.x, a10.y, a11.y));
    }
}

extern "C" void kernel_launch(void* const* d_in, const int* in_sizes, int n_in,
                              void* d_out, int out_size)
{
    const float* x     = (const float*)d_in[0];   // [8,64,128,128]
    const float* w_off = (const float*)d_in[1];   // [2,1,5,5]
    const float* b_off = (const float*)d_in[2];   // [2]
    float* out = (float*)d_out;                   // [8,64,256,256]

    float* mp;
    float* mean;
    cudaGetSymbolAddress((void**)&mp, g_meanp);
    cudaGetSymbolAddress((void**)&mean, g_mean);

    mean_partial_kernel<<<(8 * NP4) / 256, 256>>>(x, (float4*)mp);
    mean_reduce_kernel<<<NP4 / 256, 256>>>((const float4*)mp, (float4*)mean);
    carafe_fused_kernel<<<B_ * H_ / 2, 128>>>(x, mean, w_off, b_off, out);
}